// round 8
// baseline (speedup 1.0000x reference)
#include <cuda_runtime.h>
#include <cuda_bf16.h>
#include <cstdint>

#define SEQ    2048
#define EMB    256
#define HH     256
#define G4     1024      // 4*HH gate rows
#define NTAGS  12
#define TAG_START 10
#define TAG_STOP  11
#define NEGC  (-10000.0f)
#define NCHUNK 64
#define CLEN   (SEQ / NCHUNK)
#define QPAD   68                 // padded quarter stride in floats (64 + 4)
#define HBUFPAD (4 * QPAD)        // 272 floats per h buffer

// ---------------- scratch (device globals; no allocation allowed) ----------------
__device__ float g_xbuf[SEQ * EMB];            // gathered embeddings       (2 MB)
__device__ float g_pre [2 * SEQ * G4];         // input projections f/b     (16 MB)
__device__ float g_hs  [2 * SEQ * HH];         // hidden states f/b         (4 MB)
__device__ float g_feats[SEQ * NTAGS];         // emissions
__device__ float g_crfT[NCHUNK][NTAGS][NTAGS]; // per-chunk CRF transfer matrices
__device__ int   g_dummy;

__device__ __forceinline__ uint32_t smem_u32(const void* p) {
    return (uint32_t)__cvta_generic_to_shared(p);
}

__device__ __forceinline__ float htanh(float x) {
    float y;
    asm("tanh.approx.f32 %0, %1;" : "=f"(y) : "f"(x));
    return y;
}
__device__ __forceinline__ float hsigmoid(float x) {
    return fmaf(0.5f, htanh(0.5f * x), 0.5f);
}

__device__ __forceinline__ void fma2(unsigned long long& d,
                                     unsigned long long a, unsigned long long b) {
    asm("fma.rn.f32x2 %0, %1, %2, %0;" : "+l"(d) : "l"(a), "l"(b));
}

// ---------------- kernel 0: embedding gather ----------------
__global__ void gather_x_kernel(const float* __restrict__ embed,
                                const int* __restrict__ sent) {
    int t = blockIdx.x;
    int k = threadIdx.x;
    long row = (long)sent[t];
    float4 v = reinterpret_cast<const float4*>(embed + row * EMB)[k];
    reinterpret_cast<float4*>(g_xbuf + t * EMB)[k] = v;
}

// ---------------- kernel 1: pre = x @ Wih^T + bih + bhh  (both dirs) ----------------
__global__ void gemm_pre_kernel(const float* __restrict__ WihF, const float* __restrict__ WihB,
                                const float* __restrict__ bihF, const float* __restrict__ bhhF,
                                const float* __restrict__ bihB, const float* __restrict__ bhhB) {
    const int dir = blockIdx.z;
    const int r0  = blockIdx.x * 64;
    const int t0  = blockIdx.y * 64;
    const float* __restrict__ Wih = dir ? WihB : WihF;
    const float* __restrict__ bih = dir ? bihB : bihF;
    const float* __restrict__ bhh = dir ? bhhB : bhhF;

    __shared__ float Ws[32][65];
    __shared__ float Xs[32][65];

    const int tid = threadIdx.x;
    const int tx = tid & 15;
    const int ty = tid >> 4;
    float acc[4][4] = {};

    for (int kc = 0; kc < EMB; kc += 32) {
#pragma unroll
        for (int i = 0; i < 8; i++) {
            int f = tid + i * 256;
            int k = f & 31, r = f >> 5;
            Ws[k][r] = Wih[(r0 + r) * EMB + kc + k];
            Xs[k][r] = g_xbuf[(t0 + r) * EMB + kc + k];
        }
        __syncthreads();
#pragma unroll
        for (int k = 0; k < 32; k++) {
            float wv[4], xv[4];
#pragma unroll
            for (int i = 0; i < 4; i++) wv[i] = Ws[k][ty * 4 + i];
#pragma unroll
            for (int j = 0; j < 4; j++) xv[j] = Xs[k][tx * 4 + j];
#pragma unroll
            for (int i = 0; i < 4; i++)
#pragma unroll
                for (int j = 0; j < 4; j++)
                    acc[i][j] = fmaf(wv[i], xv[j], acc[i][j]);
        }
        __syncthreads();
    }
    float b[4];
#pragma unroll
    for (int i = 0; i < 4; i++) {
        int r = r0 + ty * 4 + i;
        b[i] = bih[r] + bhh[r];
    }
    float* preD = g_pre + (size_t)dir * SEQ * G4;
#pragma unroll
    for (int j = 0; j < 4; j++) {
        int t = t0 + tx * 4 + j;
        float4 v;
        v.x = acc[0][j] + b[0];
        v.y = acc[1][j] + b[1];
        v.z = acc[2][j] + b[2];
        v.w = acc[3][j] + b[3];
        *reinterpret_cast<float4*>(preD + (size_t)t * G4 + r0 + ty * 4) = v;
    }
}

// ---------------- dummy kernel (launch-slot shim so ncu captures the lstm kernel) ----------------
__global__ void dummy_kernel() {
    if (threadIdx.x == 0) g_dummy = 1;
}

// ---------------- kernel 2: LSTM recurrence ----------------
// R7 + (a) padded hbuf (68-float quarters): linear immediate-offset LDS.128,
// conflict-free across the 4 kq groups WITHOUT stagger ALU; (b) broadcast via
// 8x cp.async.bulk S2S-cluster (128B per peer) instead of 64x st.async.v4 --
// one DSM transaction per destination, far less receiver-side mbar processing.
__global__ void __launch_bounds__(512, 1) __cluster_dims__(8, 1, 1)
lstm_rec_kernel(const float* __restrict__ WhhF, const float* __restrict__ WhhB,
                const float* __restrict__ h0, const float* __restrict__ c0) {
    const int tid = threadIdx.x;
    const int w   = tid >> 5;
    const int l   = tid & 31;
    const int crank = blockIdx.x & 7;       // rank within cluster
    const int dir   = blockIdx.x >> 3;      // 0 = forward, 1 = backward
    const int u0    = crank * 32;           // first hidden unit owned by this CTA

    const float* __restrict__ Whh = dir ? WhhB : WhhF;
    const float* __restrict__ pre = g_pre + (size_t)dir * SEQ * G4;
    float* __restrict__ hs = g_hs + (size_t)dir * SEQ * HH;

    __shared__ __align__(16) float hbuf[2][HBUFPAD];
    __shared__ float gate_s[128];
    __shared__ __align__(16) float stage[2][32];
    __shared__ __align__(8) unsigned long long mbar[2];

    // init: every CTA loads the FULL initial h locally (padded layout)
    if (tid < HH) hbuf[0][(tid >> 6) * QPAD + (tid & 63)] = h0[dir * HH + tid];
    float creg = 0.f;
    if (tid < 32) creg = c0[dir * HH + u0 + tid];

    const uint32_t hbase = smem_u32(&hbuf[0][0]);
    const uint32_t mb_local[2] = { smem_u32(&mbar[0]), smem_u32(&mbar[1]) };
    const uint32_t mbDelta = mb_local[0] - hbase;

    if (tid == 0) {
        asm volatile("mbarrier.init.shared.b64 [%0], 1;" :: "r"(mb_local[0]) : "memory");
        asm volatile("mbarrier.init.shared.b64 [%0], 1;" :: "r"(mb_local[1]) : "memory");
        // pre-post expects for both mbars' phase 0 (before cluster barrier => before any send)
        asm volatile("mbarrier.arrive.expect_tx.shared.b64 _, [%0], 1024;" :: "r"(mb_local[0]) : "memory");
        asm volatile("mbarrier.arrive.expect_tx.shared.b64 _, [%0], 1024;" :: "r"(mb_local[1]) : "memory");
    }

    const int lrow = tid >> 2;                              // 0..127
    const int kq   = tid & 3;                               // k quarter
    const int grow = ((lrow >> 5) * HH) + u0 + (lrow & 31); // global gate row

    // register-resident Whh slice as f32x2 pairs (LINEAR order)
    unsigned long long w2[32];
    {
        const ulonglong2* wr = reinterpret_cast<const ulonglong2*>(Whh + (size_t)grow * HH + kq * 64);
#pragma unroll
        for (int i = 0; i < 16; i++) {
            ulonglong2 v = wr[i];
            w2[2 * i]     = v.x;
            w2[2 * i + 1] = v.y;
        }
    }

    // peer base addresses (one mapa per rank; remote addrs derived by offset)
    uint32_t pbase[8];
    if (tid < 32) {
#pragma unroll
        for (int r = 0; r < 8; r++)
            asm("mapa.shared::cluster.u32 %0, %1, %2;" : "=r"(pbase[r]) : "r"(hbase), "r"(r));
    }
    __syncthreads();
    // mbarrier inits + phase-0 expects must be cluster-visible before any send
    asm volatile("barrier.cluster.arrive.aligned;" ::: "memory");
    asm volatile("barrier.cluster.wait.aligned;"   ::: "memory");

    int pc[2] = {0, 0};   // consumed-phase counters per mbar (warp 15 only uses)

    // destination float offset of this CTA's 32-float slice inside a padded h buffer
    const uint32_t dstFloatOff = (uint32_t)((crank >> 1) * QPAD + (crank & 1) * 32);

    // prefetch pre for step 0
    float pr_cur = 0.f;
    if (kq == 0) pr_cur = __ldg(&pre[(size_t)(dir ? (SEQ - 1) : 0) * G4 + grow]);

    for (int s = 0; s < SEQ; s++) {
        const int t   = dir ? (SEQ - 1 - s) : s;
        const int cur = s & 1;
        const int nxt = cur ^ 1;

        // prefetch pre for step s+1 (hidden under a full step of work)
        float pr_nxt = 0.f;
        if (kq == 0 && s + 1 < SEQ) {
            int tn = dir ? (SEQ - 2 - s) : (s + 1);
            pr_nxt = __ldg(&pre[(size_t)tn * G4 + grow]);
        }

        if (s > 0) {
            if (w == 15) {
                // SOLE mbarrier waiter
                uint32_t parity = (uint32_t)(pc[cur] & 1);
                pc[cur]++;
                uint32_t mb = mb_local[cur];
                uint32_t done;
                asm volatile(
                    "{\n\t.reg .pred p;\n\t"
                    "mbarrier.try_wait.parity.acquire.cluster.shared::cta.b64 p, [%1], %2, 0x989680;\n\t"
                    "selp.b32 %0, 1, 0, p;\n\t}"
                    : "=r"(done) : "r"(mb), "r"(parity) : "memory");
                while (!done) {
                    asm volatile(
                        "{\n\t.reg .pred p;\n\t"
                        "mbarrier.try_wait.parity.acquire.cluster.shared::cta.b64 p, [%1], %2, 0x989680;\n\t"
                        "selp.b32 %0, 1, 0, p;\n\t}"
                        : "=r"(done) : "r"(mb), "r"(parity) : "memory");
                }
                // repost expect for this mbar's NEXT phase (causally safe)
                if (l == 0)
                    asm volatile("mbarrier.arrive.expect_tx.shared.b64 _, [%0], 1024;" :: "r"(mb) : "memory");
                // release the other 15 warps via HW barrier broadcast
                asm volatile("bar.arrive 2, 512;" ::: "memory");
            } else {
                asm volatile("bar.sync 2, 512;" ::: "memory");
            }
        }

        // ---- gemv: linear reads from the padded quarter (immediate offsets) ----
        const ulonglong2* hp = reinterpret_cast<const ulonglong2*>(&hbuf[cur][kq * QPAD]);
        unsigned long long a0 = 0, a1 = 0;
#pragma unroll
        for (int i = 0; i < 16; i++) {
            ulonglong2 hv = hp[i];
            fma2(a0, w2[2 * i],     hv.x);
            fma2(a1, w2[2 * i + 1], hv.y);
        }
        asm("add.rn.f32x2 %0, %0, %1;" : "+l"(a0) : "l"(a1));
        uint32_t lo, hi;
        asm("mov.b64 {%0, %1}, %2;" : "=r"(lo), "=r"(hi) : "l"(a0));
        float acc = __uint_as_float(lo) + __uint_as_float(hi);
        acc += __shfl_xor_sync(0xffffffffu, acc, 1);
        acc += __shfl_xor_sync(0xffffffffu, acc, 2);
        if (kq == 0) gate_s[lrow] = acc + pr_cur;

        if (tid >= 32) {
            // producers (warps 1..15): hand off and proceed (warp15 -> mbar wait)
            asm volatile("bar.arrive 1, 512;" ::: "memory");
        } else {
            asm volatile("bar.sync 1, 512;" ::: "memory");
            float gi = gate_s[tid];
            float gf = gate_s[32 + tid];
            float gg = gate_s[64 + tid];
            float go = gate_s[96 + tid];
            gi = hsigmoid(gi);
            gf = hsigmoid(gf);
            gg = htanh(gg);
            go = hsigmoid(go);
            creg = gf * creg + gi * gg;
            float hv = go * htanh(creg);

            if (s != SEQ - 1) {
                // stage the 32 h values, then ONE 128B bulk copy per peer
                stage[cur][tid] = hv;
                __syncwarp();
                asm volatile("fence.proxy.async.shared::cta;" ::: "memory");
                if (tid < 8) {
                    uint32_t dst = pbase[tid] + (uint32_t)(nxt * HBUFPAD * 4) + dstFloatOff * 4;
                    uint32_t ma  = pbase[tid] + mbDelta + (uint32_t)(nxt * 8);
                    uint32_t src = smem_u32(&stage[cur][0]);
                    asm volatile(
                        "cp.async.bulk.shared::cluster.shared::cta.mbarrier::complete_tx::bytes [%0], [%1], 128, [%2];"
                        :: "r"(dst), "r"(src), "r"(ma) : "memory");
                }
            }
            hs[(size_t)t * HH + u0 + tid] = hv;
        }
        pr_cur = pr_nxt;
    }

    asm volatile("barrier.cluster.arrive.aligned;" ::: "memory");
    asm volatile("barrier.cluster.wait.aligned;"   ::: "memory");
}

// ---------------- kernel 3: feats = [hf|hb] @ W_out^T + b_out ----------------
__global__ void feats_kernel(const float* __restrict__ Wout, const float* __restrict__ bout) {
    int gid = blockIdx.x * 256 + threadIdx.x;     // < 24576 exactly
    int t = gid / NTAGS, n = gid % NTAGS;
    const float4* hf = reinterpret_cast<const float4*>(g_hs + (size_t)t * HH);
    const float4* hb = reinterpret_cast<const float4*>(g_hs + (size_t)SEQ * HH + (size_t)t * HH);
    const float4* w0 = reinterpret_cast<const float4*>(Wout + (size_t)n * 512);
    const float4* w1 = reinterpret_cast<const float4*>(Wout + (size_t)n * 512 + 256);
    float acc = bout[n];
#pragma unroll 8
    for (int j = 0; j < 64; j++) {
        float4 a = hf[j], w = w0[j];
        acc = fmaf(a.x, w.x, fmaf(a.y, w.y, fmaf(a.z, w.z, fmaf(a.w, w.w, acc))));
    }
#pragma unroll 8
    for (int j = 0; j < 64; j++) {
        float4 a = hb[j], w = w1[j];
        acc = fmaf(a.x, w.x, fmaf(a.y, w.y, fmaf(a.z, w.z, fmaf(a.w, w.w, acc))));
    }
    g_feats[gid] = acc;
}

// ---------------- kernel 4a: per-chunk CRF transfer matrices ----------------
__global__ void crf_chunk_kernel(const float* __restrict__ trans) {
    const int c   = blockIdx.x;
    const int tid = threadIdx.x;          // < 144
    const int jo  = tid / NTAGS;
    const int ji  = tid % NTAGS;

    __shared__ float m_s[2][NTAGS][NTAGS];

    float tr[NTAGS];
#pragma unroll
    for (int p = 0; p < NTAGS; p++) tr[p] = trans[jo * NTAGS + p];

    float m = (jo == ji) ? 0.0f : NEGC;

    for (int step = 0; step < CLEN; step++) {
        int buf = step & 1;
        m_s[buf][jo][ji] = m;
        __syncthreads();
        float emit = g_feats[(c * CLEN + step) * NTAGS + jo];
        float mx = m_s[buf][0][ji] + tr[0];
#pragma unroll
        for (int p = 1; p < NTAGS; p++) mx = fmaxf(mx, m_s[buf][p][ji] + tr[p]);
        float ssum = 0.0f;
#pragma unroll
        for (int p = 0; p < NTAGS; p++) ssum += __expf(m_s[buf][p][ji] + tr[p] - mx);
        m = mx + __logf(ssum) + emit;
    }
    g_crfT[c][jo][ji] = m;
}

// ---------------- kernel 4b: fold chunk matrices + gold score -> loss ----------------
__global__ void crf_fold_kernel(const float* __restrict__ trans,
                                const int* __restrict__ tags,
                                float* __restrict__ out) {
    const int lane = threadIdx.x;
    float fv = (lane == TAG_START) ? 0.0f : NEGC;

    for (int c = 0; c < NCHUNK; c++) {
        float trow[NTAGS];
        if (lane < NTAGS) {
#pragma unroll
            for (int p = 0; p < NTAGS; p++) trow[p] = g_crfT[c][lane][p];
        } else {
#pragma unroll
            for (int p = 0; p < NTAGS; p++) trow[p] = NEGC;
        }
        float v[NTAGS];
#pragma unroll
        for (int p = 0; p < NTAGS; p++)
            v[p] = __shfl_sync(0xffffffffu, fv, p) + trow[p];
        float mx = v[0];
#pragma unroll
        for (int p = 1; p < NTAGS; p++) mx = fmaxf(mx, v[p]);
        float ssum = 0.0f;
#pragma unroll
        for (int p = 0; p < NTAGS; p++) ssum += __expf(v[p] - mx);
        float nf = mx + __logf(ssum);
        if (lane < NTAGS) fv = nf;
    }

    float sv = fv + ((lane < NTAGS) ? trans[TAG_STOP * NTAGS + lane] : 0.0f);
    float vv[NTAGS];
#pragma unroll
    for (int p = 0; p < NTAGS; p++)
        vv[p] = __shfl_sync(0xffffffffu, sv, p);
    float mx = vv[0];
#pragma unroll
    for (int p = 1; p < NTAGS; p++) mx = fmaxf(mx, vv[p]);
    float ssum = 0.0f;
#pragma unroll
    for (int p = 0; p < NTAGS; p++) ssum += __expf(vv[p] - mx);
    float fwd = mx + __logf(ssum);

    float gs = 0.0f;
    for (int t = lane; t < SEQ; t += 32) {
        int tg = tags[t];
        int pv = (t == 0) ? TAG_START : tags[t - 1];
        gs += trans[tg * NTAGS + pv] + g_feats[t * NTAGS + tg];
    }
#pragma unroll
    for (int o = 16; o; o >>= 1) gs += __shfl_xor_sync(0xffffffffu, gs, o);

    if (lane == 0) {
        gs += trans[TAG_STOP * NTAGS + tags[SEQ - 1]];
        out[0] = fwd - gs;
    }
}

// ---------------- launch ----------------
extern "C" void kernel_launch(void* const* d_in, const int* in_sizes, int n_in,
                              void* d_out, int out_size) {
    const int*   sent  = (const int*)  d_in[0];
    const int*   tags  = (const int*)  d_in[1];
    const float* embed = (const float*)d_in[2];
    const float* WihF  = (const float*)d_in[3];
    const float* WhhF  = (const float*)d_in[4];
    const float* bihF  = (const float*)d_in[5];
    const float* bhhF  = (const float*)d_in[6];
    const float* WihB  = (const float*)d_in[7];
    const float* WhhB  = (const float*)d_in[8];
    const float* bihB  = (const float*)d_in[9];
    const float* bhhB  = (const float*)d_in[10];
    const float* Wout  = (const float*)d_in[11];
    const float* bout  = (const float*)d_in[12];

    int iTrans = 15, iH0 = 13, iC0 = 14;
    if (in_sizes[13] == 144) { iTrans = 13; iH0 = 14; iC0 = 15; }
    const float* trans = (const float*)d_in[iTrans];
    const float* h0    = (const float*)d_in[iH0];
    const float* c0    = (const float*)d_in[iC0];

    float* out = (float*)d_out;

    gather_x_kernel<<<SEQ, 64>>>(embed, sent);
    gemm_pre_kernel<<<dim3(16, 32, 2), 256>>>(WihF, WihB, bihF, bhhF, bihB, bhhB);
    dummy_kernel<<<1, 32>>>();   // launch-slot shim: keeps lstm_rec in ncu's capture slot
    lstm_rec_kernel<<<16, 512>>>(WhhF, WhhB, h0, c0);
    feats_kernel<<<96, 256>>>(Wout, bout);
    crf_chunk_kernel<<<NCHUNK, 144>>>(trans);
    crf_fold_kernel<<<1, 32>>>(trans, tags, out);
}

// round 9
// speedup vs baseline: 1.2931x; 1.2931x over previous
#include <cuda_runtime.h>
#include <cuda_bf16.h>
#include <cstdint>

#define SEQ    2048
#define EMB    256
#define HH     256
#define G4     1024      // 4*HH gate rows
#define NTAGS  12
#define TAG_START 10
#define TAG_STOP  11
#define NEGC  (-10000.0f)
#define NCHUNK 64
#define CLEN   (SEQ / NCHUNK)
#define CL     16                  // cluster size (CTAs per direction)
#define EPAD   36                  // padded eighth stride in floats (32 + 4)
#define HBUFPAD (8 * EPAD)         // 288 floats per h buffer

// ---------------- scratch (device globals; no allocation allowed) ----------------
__device__ float g_xbuf[SEQ * EMB];            // gathered embeddings       (2 MB)
__device__ float g_pre [2 * SEQ * G4];         // input projections f/b     (16 MB)
__device__ float g_hs  [2 * SEQ * HH];         // hidden states f/b         (4 MB)
__device__ float g_feats[SEQ * NTAGS];         // emissions
__device__ float g_crfT[NCHUNK][NTAGS][NTAGS]; // per-chunk CRF transfer matrices
__device__ int   g_dummy;

__device__ __forceinline__ uint32_t smem_u32(const void* p) {
    return (uint32_t)__cvta_generic_to_shared(p);
}

__device__ __forceinline__ float htanh(float x) {
    float y;
    asm("tanh.approx.f32 %0, %1;" : "=f"(y) : "f"(x));
    return y;
}
__device__ __forceinline__ float hsigmoid(float x) {
    return fmaf(0.5f, htanh(0.5f * x), 0.5f);
}

__device__ __forceinline__ void fma2(unsigned long long& d,
                                     unsigned long long a, unsigned long long b) {
    asm("fma.rn.f32x2 %0, %1, %2, %0;" : "+l"(d) : "l"(a), "l"(b));
}

// ---------------- kernel 0: embedding gather ----------------
__global__ void gather_x_kernel(const float* __restrict__ embed,
                                const int* __restrict__ sent) {
    int t = blockIdx.x;
    int k = threadIdx.x;
    long row = (long)sent[t];
    float4 v = reinterpret_cast<const float4*>(embed + row * EMB)[k];
    reinterpret_cast<float4*>(g_xbuf + t * EMB)[k] = v;
}

// ---------------- kernel 1: pre = x @ Wih^T + bih + bhh  (both dirs) ----------------
__global__ void gemm_pre_kernel(const float* __restrict__ WihF, const float* __restrict__ WihB,
                                const float* __restrict__ bihF, const float* __restrict__ bhhF,
                                const float* __restrict__ bihB, const float* __restrict__ bhhB) {
    const int dir = blockIdx.z;
    const int r0  = blockIdx.x * 64;
    const int t0  = blockIdx.y * 64;
    const float* __restrict__ Wih = dir ? WihB : WihF;
    const float* __restrict__ bih = dir ? bihB : bihF;
    const float* __restrict__ bhh = dir ? bhhB : bhhF;

    __shared__ float Ws[32][65];
    __shared__ float Xs[32][65];

    const int tid = threadIdx.x;
    const int tx = tid & 15;
    const int ty = tid >> 4;
    float acc[4][4] = {};

    for (int kc = 0; kc < EMB; kc += 32) {
#pragma unroll
        for (int i = 0; i < 8; i++) {
            int f = tid + i * 256;
            int k = f & 31, r = f >> 5;
            Ws[k][r] = Wih[(r0 + r) * EMB + kc + k];
            Xs[k][r] = g_xbuf[(t0 + r) * EMB + kc + k];
        }
        __syncthreads();
#pragma unroll
        for (int k = 0; k < 32; k++) {
            float wv[4], xv[4];
#pragma unroll
            for (int i = 0; i < 4; i++) wv[i] = Ws[k][ty * 4 + i];
#pragma unroll
            for (int j = 0; j < 4; j++) xv[j] = Xs[k][tx * 4 + j];
#pragma unroll
            for (int i = 0; i < 4; i++)
#pragma unroll
                for (int j = 0; j < 4; j++)
                    acc[i][j] = fmaf(wv[i], xv[j], acc[i][j]);
        }
        __syncthreads();
    }
    float b[4];
#pragma unroll
    for (int i = 0; i < 4; i++) {
        int r = r0 + ty * 4 + i;
        b[i] = bih[r] + bhh[r];
    }
    float* preD = g_pre + (size_t)dir * SEQ * G4;
#pragma unroll
    for (int j = 0; j < 4; j++) {
        int t = t0 + tx * 4 + j;
        float4 v;
        v.x = acc[0][j] + b[0];
        v.y = acc[1][j] + b[1];
        v.z = acc[2][j] + b[2];
        v.w = acc[3][j] + b[3];
        *reinterpret_cast<float4*>(preD + (size_t)t * G4 + r0 + ty * 4) = v;
    }
}

// ---------------- dummy kernel (launch-slot shim so ncu captures the lstm kernel) ----------------
__global__ void dummy_kernel() {
    if (threadIdx.x == 0) g_dummy = 1;
}

// ---------------- kernel 2: LSTM recurrence, 16-CTA cluster per direction ----------------
// Each CTA owns 16 units (64 gate rows); per-SMSP FFMA2 issue floor halves vs the
// 8-CTA version. Comm identical in shape to R7: 64 x 16B st.async.v4 per receiver
// mbar (expect_tx 1024B = 16 senders x 64B), single-waiter warp15 + bar2 fan-out,
// producer bar.arrive(1) funnel into activation warp 0. hbuf padded at 36-float
// eighth stride (conflict-free linear LDS.128).
__global__ void __launch_bounds__(512, 1) __cluster_dims__(CL, 1, 1)
lstm_rec_kernel(const float* __restrict__ WhhF, const float* __restrict__ WhhB,
                const float* __restrict__ h0, const float* __restrict__ c0) {
    const int tid = threadIdx.x;
    const int w   = tid >> 5;
    const int l   = tid & 31;
    const int crank = blockIdx.x & (CL - 1);   // rank within cluster
    const int dir   = blockIdx.x >> 4;         // 0 = forward, 1 = backward
    const int u0    = crank * 16;              // first hidden unit owned by this CTA

    const float* __restrict__ Whh = dir ? WhhB : WhhF;
    const float* __restrict__ pre = g_pre + (size_t)dir * SEQ * G4;
    float* __restrict__ hs = g_hs + (size_t)dir * SEQ * HH;

    __shared__ __align__(16) float hbuf[2][HBUFPAD];
    __shared__ float gate_s[64];
    __shared__ __align__(16) float stage[2][16];
    __shared__ __align__(8) unsigned long long mbar[2];

    // init: every CTA loads the FULL initial h locally (padded eighth layout)
    if (tid < HH) hbuf[0][(tid >> 5) * EPAD + (tid & 31)] = h0[dir * HH + tid];
    float creg = 0.f;
    if (tid < 16) creg = c0[dir * HH + u0 + tid];

    const uint32_t hbase = smem_u32(&hbuf[0][0]);
    const uint32_t mb_local[2] = { smem_u32(&mbar[0]), smem_u32(&mbar[1]) };
    const uint32_t mbDelta = mb_local[0] - hbase;

    if (tid == 0) {
        asm volatile("mbarrier.init.shared.b64 [%0], 1;" :: "r"(mb_local[0]) : "memory");
        asm volatile("mbarrier.init.shared.b64 [%0], 1;" :: "r"(mb_local[1]) : "memory");
        // pre-post expects for both mbars' phase 0 (before cluster barrier => before any send)
        asm volatile("mbarrier.arrive.expect_tx.shared.b64 _, [%0], 1024;" :: "r"(mb_local[0]) : "memory");
        asm volatile("mbarrier.arrive.expect_tx.shared.b64 _, [%0], 1024;" :: "r"(mb_local[1]) : "memory");
    }

    const int lrow = tid >> 3;                              // 0..63 local gate row
    const int ko   = tid & 7;                               // k eighth (32 wide)
    const int grow = ((lrow >> 4) * HH) + u0 + (lrow & 15); // global gate row

    // register-resident Whh slice as f32x2 pairs (linear order)
    unsigned long long w2[16];
    {
        const ulonglong2* wr = reinterpret_cast<const ulonglong2*>(Whh + (size_t)grow * HH + ko * 32);
#pragma unroll
        for (int i = 0; i < 8; i++) {
            ulonglong2 v = wr[i];
            w2[2 * i]     = v.x;
            w2[2 * i + 1] = v.y;
        }
    }

    // peer base addresses + precomputed send addresses (warp 0 only)
    uint32_t ma0 = 0, ma1 = 0, da00 = 0, da01 = 0, da10 = 0, da11 = 0;
    int p1 = 0;
    if (w == 0) {
        int s_rank = l & 15;
        p1 = l >> 4;                          // first packet index (0/1); second = p1+2
        uint32_t pb;
        asm("mapa.shared::cluster.u32 %0, %1, %2;" : "=r"(pb) : "r"(hbase), "r"(s_rank));
        uint32_t myDstB = (uint32_t)(((crank >> 1) * EPAD + (crank & 1) * 16) * 4);
        ma0  = pb + mbDelta;
        ma1  = pb + mbDelta + 8;
        da00 = pb + myDstB + (uint32_t)p1 * 16;          // parity 0, packet p1
        da01 = da00 + 32;                                 // parity 0, packet p1+2
        da10 = pb + (uint32_t)(HBUFPAD * 4) + myDstB + (uint32_t)p1 * 16;
        da11 = da10 + 32;
    }
    __syncthreads();
    // mbarrier inits + phase-0 expects must be cluster-visible before any send
    asm volatile("barrier.cluster.arrive.aligned;" ::: "memory");
    asm volatile("barrier.cluster.wait.aligned;"   ::: "memory");

    int pc[2] = {0, 0};   // consumed-phase counters per mbar (warp 15 uses)

    // prefetch pre for step 0
    float pr_cur = 0.f;
    if (ko == 0) pr_cur = __ldg(&pre[(size_t)(dir ? (SEQ - 1) : 0) * G4 + grow]);

    for (int s = 0; s < SEQ; s++) {
        const int t   = dir ? (SEQ - 1 - s) : s;
        const int cur = s & 1;
        const int nxt = cur ^ 1;

        // prefetch pre for step s+1 (hidden under a full step of work)
        float pr_nxt = 0.f;
        if (ko == 0 && s + 1 < SEQ) {
            int tn = dir ? (SEQ - 2 - s) : (s + 1);
            pr_nxt = __ldg(&pre[(size_t)tn * G4 + grow]);
        }

        if (s > 0) {
            if (w == 15) {
                // SOLE mbarrier waiter
                uint32_t parity = (uint32_t)(pc[cur] & 1);
                pc[cur]++;
                uint32_t mb = mb_local[cur];
                uint32_t done;
                asm volatile(
                    "{\n\t.reg .pred p;\n\t"
                    "mbarrier.try_wait.parity.acquire.cluster.shared::cta.b64 p, [%1], %2, 0x989680;\n\t"
                    "selp.b32 %0, 1, 0, p;\n\t}"
                    : "=r"(done) : "r"(mb), "r"(parity) : "memory");
                while (!done) {
                    asm volatile(
                        "{\n\t.reg .pred p;\n\t"
                        "mbarrier.try_wait.parity.acquire.cluster.shared::cta.b64 p, [%1], %2, 0x989680;\n\t"
                        "selp.b32 %0, 1, 0, p;\n\t}"
                        : "=r"(done) : "r"(mb), "r"(parity) : "memory");
                }
                // repost expect for this mbar's NEXT phase (causally safe: any
                // producer's next-phase tx depends on MY CTA's upcoming send)
                if (l == 0)
                    asm volatile("mbarrier.arrive.expect_tx.shared.b64 _, [%0], 1024;" :: "r"(mb) : "memory");
                asm volatile("bar.arrive 2, 512;" ::: "memory");
            } else {
                asm volatile("bar.sync 2, 512;" ::: "memory");
            }
        }

        // ---- gemv: 32-wide k eighth, linear padded reads ----
        const ulonglong2* hp = reinterpret_cast<const ulonglong2*>(&hbuf[cur][ko * EPAD]);
        unsigned long long a0 = 0, a1 = 0;
#pragma unroll
        for (int i = 0; i < 8; i++) {
            ulonglong2 hv = hp[i];
            fma2(a0, w2[2 * i],     hv.x);
            fma2(a1, w2[2 * i + 1], hv.y);
        }
        asm("add.rn.f32x2 %0, %0, %1;" : "+l"(a0) : "l"(a1));
        uint32_t lo, hi;
        asm("mov.b64 {%0, %1}, %2;" : "=r"(lo), "=r"(hi) : "l"(a0));
        float acc = __uint_as_float(lo) + __uint_as_float(hi);
        acc += __shfl_xor_sync(0xffffffffu, acc, 1);
        acc += __shfl_xor_sync(0xffffffffu, acc, 2);
        acc += __shfl_xor_sync(0xffffffffu, acc, 4);
        if (ko == 0) gate_s[lrow] = acc + pr_cur;

        if (tid >= 32) {
            // producers (warps 1..15): hand off and proceed (warp15 -> mbar wait)
            asm volatile("bar.arrive 1, 512;" ::: "memory");
        } else {
            asm volatile("bar.sync 1, 512;" ::: "memory");
            float hv = 0.f;
            if (l < 16) {
                float gi = gate_s[l];
                float gf = gate_s[16 + l];
                float gg = gate_s[32 + l];
                float go = gate_s[48 + l];
                gi = hsigmoid(gi);
                gf = hsigmoid(gf);
                gg = htanh(gg);
                go = hsigmoid(go);
                creg = gf * creg + gi * gg;
                hv = go * htanh(creg);
                stage[cur][l] = hv;
            }
            __syncwarp();
            if (s != SEQ - 1) {
                const float4* sp = reinterpret_cast<const float4*>(&stage[cur][0]);
                float4 v0 = sp[p1];
                float4 v1 = sp[p1 + 2];
                uint32_t ma = nxt ? ma1 : ma0;
                uint32_t dA = nxt ? da10 : da00;
                uint32_t dB = nxt ? da11 : da01;
                asm volatile(
                    "st.async.shared::cluster.mbarrier::complete_tx::bytes.v4.b32 [%0], {%1,%2,%3,%4}, [%5];"
                    :: "r"(dA), "r"(__float_as_uint(v0.x)), "r"(__float_as_uint(v0.y)),
                       "r"(__float_as_uint(v0.z)), "r"(__float_as_uint(v0.w)), "r"(ma) : "memory");
                asm volatile(
                    "st.async.shared::cluster.mbarrier::complete_tx::bytes.v4.b32 [%0], {%1,%2,%3,%4}, [%5];"
                    :: "r"(dB), "r"(__float_as_uint(v1.x)), "r"(__float_as_uint(v1.y)),
                       "r"(__float_as_uint(v1.z)), "r"(__float_as_uint(v1.w)), "r"(ma) : "memory");
            }
            if (l < 16) hs[(size_t)t * HH + u0 + l] = hv;
        }
        pr_cur = pr_nxt;
    }

    asm volatile("barrier.cluster.arrive.aligned;" ::: "memory");
    asm volatile("barrier.cluster.wait.aligned;"   ::: "memory");
}

// ---------------- kernel 3: feats = [hf|hb] @ W_out^T + b_out ----------------
__global__ void feats_kernel(const float* __restrict__ Wout, const float* __restrict__ bout) {
    int gid = blockIdx.x * 256 + threadIdx.x;     // < 24576 exactly
    int t = gid / NTAGS, n = gid % NTAGS;
    const float4* hf = reinterpret_cast<const float4*>(g_hs + (size_t)t * HH);
    const float4* hb = reinterpret_cast<const float4*>(g_hs + (size_t)SEQ * HH + (size_t)t * HH);
    const float4* w0 = reinterpret_cast<const float4*>(Wout + (size_t)n * 512);
    const float4* w1 = reinterpret_cast<const float4*>(Wout + (size_t)n * 512 + 256);
    float acc = bout[n];
#pragma unroll 8
    for (int j = 0; j < 64; j++) {
        float4 a = hf[j], w = w0[j];
        acc = fmaf(a.x, w.x, fmaf(a.y, w.y, fmaf(a.z, w.z, fmaf(a.w, w.w, acc))));
    }
#pragma unroll 8
    for (int j = 0; j < 64; j++) {
        float4 a = hb[j], w = w1[j];
        acc = fmaf(a.x, w.x, fmaf(a.y, w.y, fmaf(a.z, w.z, fmaf(a.w, w.w, acc))));
    }
    g_feats[gid] = acc;
}

// ---------------- kernel 4a: per-chunk CRF transfer matrices ----------------
__global__ void crf_chunk_kernel(const float* __restrict__ trans) {
    const int c   = blockIdx.x;
    const int tid = threadIdx.x;          // < 144
    const int jo  = tid / NTAGS;
    const int ji  = tid % NTAGS;

    __shared__ float m_s[2][NTAGS][NTAGS];

    float tr[NTAGS];
#pragma unroll
    for (int p = 0; p < NTAGS; p++) tr[p] = trans[jo * NTAGS + p];

    float m = (jo == ji) ? 0.0f : NEGC;

    for (int step = 0; step < CLEN; step++) {
        int buf = step & 1;
        m_s[buf][jo][ji] = m;
        __syncthreads();
        float emit = g_feats[(c * CLEN + step) * NTAGS + jo];
        float mx = m_s[buf][0][ji] + tr[0];
#pragma unroll
        for (int p = 1; p < NTAGS; p++) mx = fmaxf(mx, m_s[buf][p][ji] + tr[p]);
        float ssum = 0.0f;
#pragma unroll
        for (int p = 0; p < NTAGS; p++) ssum += __expf(m_s[buf][p][ji] + tr[p] - mx);
        m = mx + __logf(ssum) + emit;
    }
    g_crfT[c][jo][ji] = m;
}

// ---------------- kernel 4b: fold chunk matrices + gold score -> loss ----------------
__global__ void crf_fold_kernel(const float* __restrict__ trans,
                                const int* __restrict__ tags,
                                float* __restrict__ out) {
    const int lane = threadIdx.x;
    float fv = (lane == TAG_START) ? 0.0f : NEGC;

    for (int c = 0; c < NCHUNK; c++) {
        float trow[NTAGS];
        if (lane < NTAGS) {
#pragma unroll
            for (int p = 0; p < NTAGS; p++) trow[p] = g_crfT[c][lane][p];
        } else {
#pragma unroll
            for (int p = 0; p < NTAGS; p++) trow[p] = NEGC;
        }
        float v[NTAGS];
#pragma unroll
        for (int p = 0; p < NTAGS; p++)
            v[p] = __shfl_sync(0xffffffffu, fv, p) + trow[p];
        float mx = v[0];
#pragma unroll
        for (int p = 1; p < NTAGS; p++) mx = fmaxf(mx, v[p]);
        float ssum = 0.0f;
#pragma unroll
        for (int p = 0; p < NTAGS; p++) ssum += __expf(v[p] - mx);
        float nf = mx + __logf(ssum);
        if (lane < NTAGS) fv = nf;
    }

    float sv = fv + ((lane < NTAGS) ? trans[TAG_STOP * NTAGS + lane] : 0.0f);
    float vv[NTAGS];
#pragma unroll
    for (int p = 0; p < NTAGS; p++)
        vv[p] = __shfl_sync(0xffffffffu, sv, p);
    float mx = vv[0];
#pragma unroll
    for (int p = 1; p < NTAGS; p++) mx = fmaxf(mx, vv[p]);
    float ssum = 0.0f;
#pragma unroll
    for (int p = 0; p < NTAGS; p++) ssum += __expf(vv[p] - mx);
    float fwd = mx + __logf(ssum);

    float gs = 0.0f;
    for (int t = lane; t < SEQ; t += 32) {
        int tg = tags[t];
        int pv = (t == 0) ? TAG_START : tags[t - 1];
        gs += trans[tg * NTAGS + pv] + g_feats[t * NTAGS + tg];
    }
#pragma unroll
    for (int o = 16; o; o >>= 1) gs += __shfl_xor_sync(0xffffffffu, gs, o);

    if (lane == 0) {
        gs += trans[TAG_STOP * NTAGS + tags[SEQ - 1]];
        out[0] = fwd - gs;
    }
}

// ---------------- launch ----------------
extern "C" void kernel_launch(void* const* d_in, const int* in_sizes, int n_in,
                              void* d_out, int out_size) {
    const int*   sent  = (const int*)  d_in[0];
    const int*   tags  = (const int*)  d_in[1];
    const float* embed = (const float*)d_in[2];
    const float* WihF  = (const float*)d_in[3];
    const float* WhhF  = (const float*)d_in[4];
    const float* bihF  = (const float*)d_in[5];
    const float* bhhF  = (const float*)d_in[6];
    const float* WihB  = (const float*)d_in[7];
    const float* WhhB  = (const float*)d_in[8];
    const float* bihB  = (const float*)d_in[9];
    const float* bhhB  = (const float*)d_in[10];
    const float* Wout  = (const float*)d_in[11];
    const float* bout  = (const float*)d_in[12];

    int iTrans = 15, iH0 = 13, iC0 = 14;
    if (in_sizes[13] == 144) { iTrans = 13; iH0 = 14; iC0 = 15; }
    const float* trans = (const float*)d_in[iTrans];
    const float* h0    = (const float*)d_in[iH0];
    const float* c0    = (const float*)d_in[iC0];

    float* out = (float*)d_out;

    // cluster size 16 > portable max 8: needs the nonportable attribute
    cudaFuncSetAttribute(lstm_rec_kernel,
                         cudaFuncAttributeNonPortableClusterSizeAllowed, 1);

    gather_x_kernel<<<SEQ, 64>>>(embed, sent);
    gemm_pre_kernel<<<dim3(16, 32, 2), 256>>>(WihF, WihB, bihF, bhhF, bihB, bhhB);
    dummy_kernel<<<1, 32>>>();   // launch-slot shim: keeps lstm_rec in ncu's capture slot
    lstm_rec_kernel<<<32, 512>>>(WhhF, WhhB, h0, c0);
    feats_kernel<<<96, 256>>>(Wout, bout);
    crf_chunk_kernel<<<NCHUNK, 144>>>(trans);
    crf_fold_kernel<<<1, 32>>>(trans, tags, out);
}